// round 6
// baseline (speedup 1.0000x reference)
#include <cuda_runtime.h>
#include <cuda_bf16.h>
#include <math.h>
#include <stdint.h>

// ---------------------------------------------------------------------------
// VectorQuantizerEMA  (N=32768, K=8192, D=512) — mma.sync bf16 split version
// (tcgen05 unavailable: harness emits compute_103 PTX, no 'a' target)
// ---------------------------------------------------------------------------
#define NTOK 32768
#define KCODE 8192
#define DDIM 512

#define DECAY 0.99f
#define ONE_MINUS_DECAY 0.01f
#define EPS 1e-5f
#define COMMIT 0.25f

#define OQ  ((size_t)0)
#define OL  ((size_t)(NTOK) * DDIM)
#define OP  (OL + 1)
#define OE  (OP + 1)
#define OC  (OE + (size_t)KCODE * DDIM)
#define OW  (OC + KCODE)

// ------------------------- device scratch (no alloc) -----------------------
__device__ float          g_halfE2[KCODE];
__device__ int            g_idx[NTOK];
__device__ float          g_cs[KCODE];
__device__ float          g_newcs[KCODE];
__device__ float          g_dw[(size_t)KCODE * DDIM];
__device__ double         g_loss;
__device__ __nv_bfloat16  g_xhi[(size_t)NTOK * DDIM];
__device__ __nv_bfloat16  g_xlo[(size_t)NTOK * DDIM];
__device__ __nv_bfloat16  g_ehi[(size_t)KCODE * DDIM];
__device__ __nv_bfloat16  g_elo[(size_t)KCODE * DDIM];
__device__ float          g_bv[NTOK];
__device__ float          g_sv[NTOK];
__device__ int            g_bi[NTOK];
__device__ int            g_si[NTOK];

// ------------------------- helpers -----------------------------------------
__device__ __forceinline__ uint32_t smem_u32(const void* p) {
    uint32_t a;
    asm("{ .reg .u64 t; cvta.to.shared.u64 t, %1; cvt.u32.u64 %0, t; }" : "=r"(a) : "l"(p));
    return a;
}
__device__ __forceinline__ void cp16(uint32_t dst, const void* src) {
    asm volatile("cp.async.cg.shared.global [%0], [%1], 16;" :: "r"(dst), "l"(src));
}
#define CP_COMMIT() asm volatile("cp.async.commit_group;" ::: "memory")

__device__ __forceinline__ void ldm_x4(uint32_t addr, uint32_t& r0, uint32_t& r1,
                                       uint32_t& r2, uint32_t& r3) {
    asm volatile("ldmatrix.sync.aligned.m8n8.x4.shared.b16 {%0,%1,%2,%3}, [%4];"
                 : "=r"(r0), "=r"(r1), "=r"(r2), "=r"(r3) : "r"(addr));
}
__device__ __forceinline__ void mma16816(float* d, const uint32_t* a, const uint32_t* b) {
    asm volatile("mma.sync.aligned.m16n8k16.row.col.f32.bf16.bf16.f32 "
                 "{%0,%1,%2,%3}, {%4,%5,%6,%7}, {%8,%9}, {%0,%1,%2,%3};"
                 : "+f"(d[0]), "+f"(d[1]), "+f"(d[2]), "+f"(d[3])
                 : "r"(a[0]), "r"(a[1]), "r"(a[2]), "r"(a[3]), "r"(b[0]), "r"(b[1]));
}
// merge sorted top2 (t) with sorted top2 (o)
__device__ __forceinline__ void merge2(float& t1v, int& t1i, float& t2v, int& t2i,
                                       float o1v, int o1i, float o2v, int o2i) {
    if (o1v > t1v) {
        float n2v = t1v; int n2i = t1i;
        if (o2v > n2v) { n2v = o2v; n2i = o2i; }
        t1v = o1v; t1i = o1i; t2v = n2v; t2i = n2i;
    } else if (o1v > t2v) {
        t2v = o1v; t2i = o1i;
    }
}

// ---------------------------------------------------------------------------
// K0a: per-code half-norms, E bf16 hi/lo split, zero scratch
// ---------------------------------------------------------------------------
__global__ void k_prep(const float* __restrict__ E) {
    int k = blockIdx.x;
    int t = threadIdx.x;
    const float* row = E + (size_t)k * DDIM;
    float e0 = row[t], e1 = row[t + 256];

    __nv_bfloat16 h0 = __float2bfloat16_rn(e0);
    __nv_bfloat16 h1 = __float2bfloat16_rn(e1);
    g_ehi[(size_t)k * DDIM + t]       = h0;
    g_ehi[(size_t)k * DDIM + t + 256] = h1;
    g_elo[(size_t)k * DDIM + t]       = __float2bfloat16_rn(e0 - __bfloat162float(h0));
    g_elo[(size_t)k * DDIM + t + 256] = __float2bfloat16_rn(e1 - __bfloat162float(h1));

    float s = e0 * e0 + e1 * e1;
    __shared__ float sh[8];
    int lane = t & 31, w = t >> 5;
    #pragma unroll
    for (int o = 16; o; o >>= 1) s += __shfl_down_sync(0xffffffffu, s, o);
    if (lane == 0) sh[w] = s;
    __syncthreads();
    if (w == 0) {
        float v = (lane < 8) ? sh[lane] : 0.f;
        #pragma unroll
        for (int o = 4; o; o >>= 1) v += __shfl_down_sync(0xffffffffu, v, o);
        if (lane == 0) g_halfE2[k] = 0.5f * v;
    }
    float* dwr = g_dw + (size_t)k * DDIM;
    dwr[t] = 0.f;
    dwr[t + 256] = 0.f;
    if (t == 0) g_cs[k] = 0.f;
    if (k == 0 && t == 0) g_loss = 0.0;
}

// K0b: X bf16 hi/lo split
__global__ void k_cvtx(const float* __restrict__ X) {
    size_t i = (size_t)blockIdx.x * 256 + threadIdx.x;
    float x = X[i];
    __nv_bfloat16 h = __float2bfloat16_rn(x);
    g_xhi[i] = h;
    g_xlo[i] = __float2bfloat16_rn(x - __bfloat162float(h));
}

// ---------------------------------------------------------------------------
// K1: fused mma.sync GEMM + top-2 argmax.
// CTA: 128 tokens, sweeps 64 code tiles of 128. Contraction (virtual 1536):
//   kc 0-15: Xhi.Ehi, 16-31: Xhi.Elo, 32-47: Xlo.Ehi   (BK=32)
// acc init = -halfE2[col]. 3-stage cp.async pipeline. 8 warps (4x2), 32x64.
// ---------------------------------------------------------------------------
#define BM 128
#define BN 128
#define BK 32
#define KCH 48                       // chunks per col tile
#define NTILE (KCODE / BN)           // 64
#define GTOT (NTILE * KCH)           // 3072
#define SROW 40                      // bf16 stride (32 + 8 pad) = 80 B
#define STAGE_A (BM * SROW * 2)      // 10240 B
#define STAGE_SZ (2 * STAGE_A)       // 20480 B (A then B)
#define GEMM_SMEM (3 * STAGE_SZ)     // 61440 B

__device__ __forceinline__ void load_chunk(int g, int m0, uint32_t sb, int tid) {
    const int ct = g / KCH, kc = g % KCH;
    const int n0 = ct * BN;
    const int sel = kc >> 4;                       // 0,1,2
    const int koff = (kc & 15) * BK;               // element offset in D
    const __nv_bfloat16* Asrc = (sel == 2) ? g_xlo : g_xhi;
    const __nv_bfloat16* Bsrc = (sel == 1) ? g_elo : g_ehi;
    const uint32_t stA = sb + (g % 3) * STAGE_SZ;
    const uint32_t stB = stA + STAGE_A;
    #pragma unroll
    for (int i = 0; i < 2; i++) {
        int idx = tid + i * 256;                   // 0..511
        int row = idx >> 2, c = idx & 3;
        cp16(stA + row * (SROW * 2) + c * 16,
             Asrc + (size_t)(m0 + row) * DDIM + koff + c * 8);
        cp16(stB + row * (SROW * 2) + c * 16,
             Bsrc + (size_t)(n0 + row) * DDIM + koff + c * 8);
    }
    CP_COMMIT();
}

__global__ __launch_bounds__(256, 2)
void k_gemm() {
    extern __shared__ char smem[];
    const uint32_t sb = smem_u32(smem);
    const int tid = threadIdx.x;
    const int wid = tid >> 5;
    const int lane = tid & 31;
    const int wm = wid >> 1;          // 0..3  (rows wm*32)
    const int wn = wid & 1;           // 0..1  (cols wn*64)
    const int m0 = blockIdx.x * BM;

    float acc[2][8][4];
    float t1v[4], t2v[4];
    int   t1i[4], t2i[4];
    #pragma unroll
    for (int s = 0; s < 4; s++) { t1v[s] = -3.0e38f; t2v[s] = -3.0e38f; t1i[s] = 0; t2i[s] = 0; }

    // precomputed ldmatrix lane addressing (byte offsets within stage)
    const uint32_t a_off = (uint32_t)(wm * 32 + (lane & 15)) * (SROW * 2) + (lane >> 4) * 16;
    const uint32_t b_row = (uint32_t)(wn * 64 + (lane & 7) + ((lane >> 4) << 3));
    const uint32_t b_off = b_row * (SROW * 2) + ((lane >> 3) & 1) * 16;

    load_chunk(0, m0, sb, tid);
    load_chunk(1, m0, sb, tid);
    load_chunk(2, m0, sb, tid);

    for (int g = 0; g < GTOT; ++g) {
        const int ct = g / KCH, kc = g % KCH;

        if (kc == 0) {
            const int n0 = ct * BN;
            #pragma unroll
            for (int nf = 0; nf < 8; nf++) {
                int col = n0 + wn * 64 + nf * 8 + (lane & 3) * 2;
                float2 h = *(const float2*)(&g_halfE2[col]);
                acc[0][nf][0] = -h.x; acc[0][nf][1] = -h.y;
                acc[0][nf][2] = -h.x; acc[0][nf][3] = -h.y;
                acc[1][nf][0] = -h.x; acc[1][nf][1] = -h.y;
                acc[1][nf][2] = -h.x; acc[1][nf][3] = -h.y;
            }
        }

        asm volatile("cp.async.wait_group 2;" ::: "memory");
        __syncthreads();

        const uint32_t stA = sb + (g % 3) * STAGE_SZ;
        const uint32_t stB = stA + STAGE_A;
        #pragma unroll
        for (int ks = 0; ks < 2; ks++) {
            uint32_t a[2][4];
            ldm_x4(stA + a_off + ks * 32 + 0 * (16 * SROW * 2) + (wm * 0),
                   a[0][0], a[0][1], a[0][2], a[0][3]);
            ldm_x4(stA + a_off + ks * 32 + 16 * (SROW * 2),
                   a[1][0], a[1][1], a[1][2], a[1][3]);
            uint32_t b[8][2];
            #pragma unroll
            for (int np = 0; np < 4; np++) {
                uint32_t r0, r1, r2, r3;
                ldm_x4(stB + b_off + ks * 32 + np * (16 * SROW * 2), r0, r1, r2, r3);
                b[np * 2][0] = r0; b[np * 2][1] = r1;
                b[np * 2 + 1][0] = r2; b[np * 2 + 1][1] = r3;
            }
            #pragma unroll
            for (int mf = 0; mf < 2; mf++)
                #pragma unroll
                for (int nf = 0; nf < 8; nf++)
                    mma16816(acc[mf][nf], a[mf], b[nf]);
        }
        __syncthreads();
        if (g + 3 < GTOT) load_chunk(g + 3, m0, sb, tid);

        if (kc == KCH - 1) {
            const int n0 = ct * BN;
            #pragma unroll
            for (int mf = 0; mf < 2; mf++)
                #pragma unroll
                for (int h = 0; h < 2; h++) {
                    int s = mf * 2 + h;
                    #pragma unroll
                    for (int nf = 0; nf < 8; nf++) {
                        int colb = n0 + wn * 64 + nf * 8 + (lane & 3) * 2;
                        float v0 = acc[mf][nf][h * 2 + 0];
                        float v1 = acc[mf][nf][h * 2 + 1];
                        if (v0 > t1v[s]) { t2v[s] = t1v[s]; t2i[s] = t1i[s]; t1v[s] = v0; t1i[s] = colb; }
                        else if (v0 > t2v[s]) { t2v[s] = v0; t2i[s] = colb; }
                        if (v1 > t1v[s]) { t2v[s] = t1v[s]; t2i[s] = t1i[s]; t1v[s] = v1; t1i[s] = colb + 1; }
                        else if (v1 > t2v[s]) { t2v[s] = v1; t2i[s] = colb + 1; }
                    }
                }
        }
    }

    // warp-level reduce: lanes sharing a row differ in bits 0-1
    #pragma unroll
    for (int s = 0; s < 4; s++) {
        #pragma unroll
        for (int d = 1; d <= 2; d <<= 1) {
            float o1v = __shfl_xor_sync(0xffffffffu, t1v[s], d);
            int   o1i = __shfl_xor_sync(0xffffffffu, t1i[s], d);
            float o2v = __shfl_xor_sync(0xffffffffu, t2v[s], d);
            int   o2i = __shfl_xor_sync(0xffffffffu, t2i[s], d);
            merge2(t1v[s], t1i[s], t2v[s], t2i[s], o1v, o1i, o2v, o2i);
        }
    }

    // cross-warp (warp_n 0/1) reduce through smem (stages are dead now)
    __syncthreads();
    float* c_v = (float*)smem;            // [128][2][2]
    int*   c_i = (int*)(smem + 2048);     // [128][2][2]
    if ((lane & 3) == 0) {
        #pragma unroll
        for (int s = 0; s < 4; s++) {
            int mf = s >> 1, h = s & 1;
            int row = wm * 32 + mf * 16 + h * 8 + (lane >> 2);
            c_v[(row * 2 + wn) * 2 + 0] = t1v[s];
            c_v[(row * 2 + wn) * 2 + 1] = t2v[s];
            c_i[(row * 2 + wn) * 2 + 0] = t1i[s];
            c_i[(row * 2 + wn) * 2 + 1] = t2i[s];
        }
    }
    __syncthreads();
    if (tid < BM) {
        float v1 = c_v[(tid * 2) * 2 + 0], v2 = c_v[(tid * 2) * 2 + 1];
        int   i1 = c_i[(tid * 2) * 2 + 0], i2 = c_i[(tid * 2) * 2 + 1];
        merge2(v1, i1, v2, i2,
               c_v[(tid * 2 + 1) * 2 + 0], c_i[(tid * 2 + 1) * 2 + 0],
               c_v[(tid * 2 + 1) * 2 + 1], c_i[(tid * 2 + 1) * 2 + 1]);
        g_bv[m0 + tid] = v1; g_bi[m0 + tid] = i1;
        g_sv[m0 + tid] = v2; g_si[m0 + tid] = i2;
    }
}

// ---------------------------------------------------------------------------
// K1b: exact fp32 refine of approx top-2 (one warp per token)
// ---------------------------------------------------------------------------
__global__ void k_refine(const float* __restrict__ X, const float* __restrict__ E) {
    const int n = blockIdx.x * 8 + (threadIdx.x >> 5);
    const int lane = threadIdx.x & 31;
    const int bi = g_bi[n], si = g_si[n];
    const float* x  = X + (size_t)n * DDIM;
    const float* e1 = E + (size_t)bi * DDIM;
    const float* e2 = E + (size_t)si * DDIM;
    float s1 = 0.f, s2 = 0.f;
    #pragma unroll
    for (int i = 0; i < DDIM / 32; i++) {
        float xv = x[lane + i * 32];
        s1 = fmaf(xv, e1[lane + i * 32], s1);
        s2 = fmaf(xv, e2[lane + i * 32], s2);
    }
    #pragma unroll
    for (int o = 16; o; o >>= 1) {
        s1 += __shfl_xor_sync(0xffffffffu, s1, o);
        s2 += __shfl_xor_sync(0xffffffffu, s2, o);
    }
    if (lane == 0) {
        float sc1 = s1 - g_halfE2[bi];
        float sc2 = s2 - g_halfE2[si];
        int idx = bi;
        if (sc2 > sc1 || (sc2 == sc1 && si < bi)) idx = si;
        g_idx[n] = idx;
    }
}

// ---------------------------------------------------------------------------
// K2: gather + straight-through output, loss, scatter cs/dw
// ---------------------------------------------------------------------------
__global__ void k_scatter(const float* __restrict__ X, const float* __restrict__ E,
                          float* __restrict__ out) {
    int n = blockIdx.x;
    int k = g_idx[n];
    int t = threadIdx.x;

    float4 x = *(const float4*)(X + (size_t)n * DDIM + t * 4);
    float4 q = *(const float4*)(E + (size_t)k * DDIM + t * 4);
    float dx = q.x - x.x, dy = q.y - x.y, dz = q.z - x.z, dw = q.w - x.w;
    float4 o;
    o.x = x.x + dx; o.y = x.y + dy; o.z = x.z + dz; o.w = x.w + dw;
    *(float4*)(out + OQ + (size_t)n * DDIM + t * 4) = o;

    float ls = dx * dx + dy * dy + dz * dz + dw * dw;
    __shared__ float sh[4];
    int lane = t & 31, w = t >> 5;
    #pragma unroll
    for (int oo = 16; oo; oo >>= 1) ls += __shfl_down_sync(0xffffffffu, ls, oo);
    if (lane == 0) sh[w] = ls;
    __syncthreads();
    if (t == 0) {
        float s = sh[0] + sh[1] + sh[2] + sh[3];
        atomicAdd(&g_loss, (double)s);
        atomicAdd(&g_cs[k], 1.0f);
    }

    float* dwr = g_dw + (size_t)k * DDIM + t * 4;
    atomicAdd(dwr + 0, x.x);
    atomicAdd(dwr + 1, x.y);
    atomicAdd(dwr + 2, x.z);
    atomicAdd(dwr + 3, x.w);
}

// K3: stats
__global__ __launch_bounds__(1024, 1)
void k_stats(const float* __restrict__ ema_cs, float* __restrict__ out) {
    int t = threadIdx.x;
    float pre[8];
    double s_pre = 0.0, s_ent = 0.0;
    #pragma unroll
    for (int i = 0; i < 8; i++) {
        int k = t + i * 1024;
        float cs = g_cs[k];
        pre[i] = ema_cs[k] * DECAY + ONE_MINUS_DECAY * cs;
        s_pre += (double)pre[i];
        float p = cs * (1.0f / (float)NTOK);
        s_ent += (double)(p * logf(p + 1e-10f));
    }
    __shared__ double shp[32], she[32];
    int lane = t & 31, w = t >> 5;
    #pragma unroll
    for (int o = 16; o; o >>= 1) {
        s_pre += __shfl_down_sync(0xffffffffu, s_pre, o);
        s_ent += __shfl_down_sync(0xffffffffu, s_ent, o);
    }
    if (lane == 0) { shp[w] = s_pre; she[w] = s_ent; }
    __syncthreads();
    __shared__ double tot_pre_s, tot_ent_s;
    if (w == 0) {
        double vp = shp[lane], ve = she[lane];
        #pragma unroll
        for (int o = 16; o; o >>= 1) {
            vp += __shfl_down_sync(0xffffffffu, vp, o);
            ve += __shfl_down_sync(0xffffffffu, ve, o);
        }
        if (lane == 0) { tot_pre_s = vp; tot_ent_s = ve; }
    }
    __syncthreads();
    float ntot = (float)tot_pre_s;
    float denom = ntot + (float)KCODE * EPS;
    #pragma unroll
    for (int i = 0; i < 8; i++) {
        int k = t + i * 1024;
        float ncs = (pre[i] + EPS) / denom * ntot;
        g_newcs[k] = ncs;
        out[OC + k] = ncs;
    }
    if (t == 0) {
        out[OL] = (float)(COMMIT * g_loss / ((double)NTOK * (double)DDIM));
        out[OP] = (float)exp(-tot_ent_s);
    }
}

// K4: EMA updates (float2: OE/OW only 8B aligned)
__global__ void k_ema(const float* __restrict__ ema_w, float* __restrict__ out) {
    size_t gi = (size_t)blockIdx.x * blockDim.x + threadIdx.x;
    int k = (int)(gi >> 8);
    float ncs = g_newcs[k];
    float2 w = *(const float2*)(ema_w + gi * 2);
    float2 d = *(const float2*)(g_dw + gi * 2);
    float2 ew;
    ew.x = w.x * DECAY + ONE_MINUS_DECAY * d.x;
    ew.y = w.y * DECAY + ONE_MINUS_DECAY * d.y;
    *(float2*)(out + OW + gi * 2) = ew;
    float2 eb;
    eb.x = ew.x / ncs; eb.y = ew.y / ncs;
    *(float2*)(out + OE + gi * 2) = eb;
}

// ---------------------------------------------------------------------------
extern "C" void kernel_launch(void* const* d_in, const int* in_sizes, int n_in,
                              void* d_out, int out_size) {
    const float* X   = (const float*)d_in[0];
    const float* E   = (const float*)d_in[1];
    const float* ECS = (const float*)d_in[2];
    const float* EW  = (const float*)d_in[3];
    float* out = (float*)d_out;

    cudaFuncSetAttribute(k_gemm, cudaFuncAttributeMaxDynamicSharedMemorySize, GEMM_SMEM);

    k_prep<<<KCODE, 256>>>(E);
    k_cvtx<<<(NTOK * DDIM) / 256, 256>>>(X);
    k_gemm<<<NTOK / BM, 256, GEMM_SMEM>>>();
    k_refine<<<NTOK / 8, 256>>>(X, E);
    k_scatter<<<NTOK, 128>>>(X, E, out);
    k_stats<<<1, 1024>>>(ECS, out);
    k_ema<<<(KCODE * DDIM / 2) / 256, 256>>>(EW, out);
}

// round 7
// speedup vs baseline: 1.3049x; 1.3049x over previous
#include <cuda_runtime.h>
#include <cuda_bf16.h>
#include <math.h>
#include <stdint.h>

// ---------------------------------------------------------------------------
// VectorQuantizerEMA  (N=32768, K=8192, D=512) — persistent mma.sync version
// ---------------------------------------------------------------------------
#define NTOK 32768
#define KCODE 8192
#define DDIM 512

#define DECAY 0.99f
#define ONE_MINUS_DECAY 0.01f
#define EPS 1e-5f
#define COMMIT 0.25f

#define OQ  ((size_t)0)
#define OL  ((size_t)(NTOK) * DDIM)
#define OP  (OL + 1)
#define OE  (OP + 1)
#define OC  (OE + (size_t)KCODE * DDIM)
#define OW  (OC + KCODE)

// ------------------------- device scratch (no alloc) -----------------------
__device__ float          g_halfE2[KCODE];
__device__ int            g_idx[NTOK];
__device__ float          g_cs[KCODE];
__device__ float          g_newcs[KCODE];
__device__ float          g_dw[(size_t)KCODE * DDIM];
__device__ double         g_loss;
__device__ __nv_bfloat16  g_xhi[(size_t)NTOK * DDIM];
__device__ __nv_bfloat16  g_xlo[(size_t)NTOK * DDIM];
__device__ __nv_bfloat16  g_ehi[(size_t)KCODE * DDIM];
__device__ __nv_bfloat16  g_elo[(size_t)KCODE * DDIM];
__device__ float4         g_cand[(size_t)64 * NTOK];   // [ct][token] {v1,v2,i1,i2}
__device__ unsigned int   g_work;

// ------------------------- helpers -----------------------------------------
__device__ __forceinline__ uint32_t smem_u32(const void* p) {
    uint32_t a;
    asm("{ .reg .u64 t; cvta.to.shared.u64 t, %1; cvt.u32.u64 %0, t; }" : "=r"(a) : "l"(p));
    return a;
}
__device__ __forceinline__ void cp16(uint32_t dst, const void* src) {
    asm volatile("cp.async.cg.shared.global [%0], [%1], 16;" :: "r"(dst), "l"(src));
}
#define CP_COMMIT() asm volatile("cp.async.commit_group;" ::: "memory")

__device__ __forceinline__ void ldm_x4(uint32_t addr, uint32_t& r0, uint32_t& r1,
                                       uint32_t& r2, uint32_t& r3) {
    asm volatile("ldmatrix.sync.aligned.m8n8.x4.shared.b16 {%0,%1,%2,%3}, [%4];"
                 : "=r"(r0), "=r"(r1), "=r"(r2), "=r"(r3) : "r"(addr));
}
__device__ __forceinline__ void mma16816(float* d, const uint32_t* a, const uint32_t* b) {
    asm volatile("mma.sync.aligned.m16n8k16.row.col.f32.bf16.bf16.f32 "
                 "{%0,%1,%2,%3}, {%4,%5,%6,%7}, {%8,%9}, {%0,%1,%2,%3};"
                 : "+f"(d[0]), "+f"(d[1]), "+f"(d[2]), "+f"(d[3])
                 : "r"(a[0]), "r"(a[1]), "r"(a[2]), "r"(a[3]), "r"(b[0]), "r"(b[1]));
}
__device__ __forceinline__ void merge2(float& t1v, int& t1i, float& t2v, int& t2i,
                                       float o1v, int o1i, float o2v, int o2i) {
    if (o1v > t1v) {
        float n2v = t1v; int n2i = t1i;
        if (o2v > n2v) { n2v = o2v; n2i = o2i; }
        t1v = o1v; t1i = o1i; t2v = n2v; t2i = n2i;
    } else if (o1v > t2v) {
        t2v = o1v; t2i = o1i;
    }
}

// ---------------------------------------------------------------------------
// K0a: per-code half-norms, E bf16 hi/lo split, zero scratch, reset work queue
// ---------------------------------------------------------------------------
__global__ void k_prep(const float* __restrict__ E) {
    int k = blockIdx.x;
    int t = threadIdx.x;
    const float* row = E + (size_t)k * DDIM;
    float e0 = row[t], e1 = row[t + 256];

    __nv_bfloat16 h0 = __float2bfloat16_rn(e0);
    __nv_bfloat16 h1 = __float2bfloat16_rn(e1);
    g_ehi[(size_t)k * DDIM + t]       = h0;
    g_ehi[(size_t)k * DDIM + t + 256] = h1;
    g_elo[(size_t)k * DDIM + t]       = __float2bfloat16_rn(e0 - __bfloat162float(h0));
    g_elo[(size_t)k * DDIM + t + 256] = __float2bfloat16_rn(e1 - __bfloat162float(h1));

    float s = e0 * e0 + e1 * e1;
    __shared__ float sh[8];
    int lane = t & 31, w = t >> 5;
    #pragma unroll
    for (int o = 16; o; o >>= 1) s += __shfl_down_sync(0xffffffffu, s, o);
    if (lane == 0) sh[w] = s;
    __syncthreads();
    if (w == 0) {
        float v = (lane < 8) ? sh[lane] : 0.f;
        #pragma unroll
        for (int o = 4; o; o >>= 1) v += __shfl_down_sync(0xffffffffu, v, o);
        if (lane == 0) g_halfE2[k] = 0.5f * v;
    }
    float* dwr = g_dw + (size_t)k * DDIM;
    dwr[t] = 0.f;
    dwr[t + 256] = 0.f;
    if (t == 0) g_cs[k] = 0.f;
    if (k == 0 && t == 0) { g_loss = 0.0; g_work = 0u; }
}

// K0b: X bf16 hi/lo split
__global__ void k_cvtx(const float* __restrict__ X) {
    size_t i = (size_t)blockIdx.x * 256 + threadIdx.x;
    float x = X[i];
    __nv_bfloat16 h = __float2bfloat16_rn(x);
    g_xhi[i] = h;
    g_xlo[i] = __float2bfloat16_rn(x - __bfloat162float(h));
}

// ---------------------------------------------------------------------------
// K1: persistent fused mma.sync GEMM + per-tile top-2.
// Work item = (m-tile 0..255, ct 0..63): 128x128 output tile, 48 BK=32 chunks
// (virtual K=1536: kc 0-15 Xhi.Ehi, 16-31 Xhi.Elo, 32-47 Xlo.Ehi).
// 296 persistent CTAs, occ 2, 8 warps (4x2), warp tile 32x64.
// 4-stage cp.async pipeline, ONE __syncthreads per chunk.
// ---------------------------------------------------------------------------
#define BM 128
#define BN 128
#define BK 32
#define KCH 48
#define NITEMS (256 * 64)
#define SROW 40                      // bf16 stride (32 + 8 pad) = 80 B
#define STAGE_A (BM * SROW * 2)      // 10240 B
#define STAGE_SZ (2 * STAGE_A)       // 20480 B
#define NSTAGE 4
#define GEMM_SMEM (NSTAGE * STAGE_SZ) // 81920 B

__device__ __forceinline__ void load_chunk(int kc, int slot, int m0, int n0,
                                           uint32_t sb, int tid) {
    const int sel = kc >> 4;                       // 0,1,2
    const int koff = (kc & 15) * BK;
    const __nv_bfloat16* Asrc = (sel == 2) ? g_xlo : g_xhi;
    const __nv_bfloat16* Bsrc = (sel == 1) ? g_elo : g_ehi;
    const uint32_t stA = sb + slot * STAGE_SZ;
    const uint32_t stB = stA + STAGE_A;
    #pragma unroll
    for (int i = 0; i < 2; i++) {
        int idx = tid + i * 256;
        int row = idx >> 2, c = idx & 3;
        cp16(stA + row * (SROW * 2) + c * 16,
             Asrc + (size_t)(m0 + row) * DDIM + koff + c * 8);
        cp16(stB + row * (SROW * 2) + c * 16,
             Bsrc + (size_t)(n0 + row) * DDIM + koff + c * 8);
    }
    CP_COMMIT();
}

__global__ __launch_bounds__(256, 2)
void k_gemm() {
    extern __shared__ char smem[];
    const uint32_t sb = smem_u32(smem);
    const int tid = threadIdx.x;
    const int wid = tid >> 5;
    const int lane = tid & 31;
    const int wm = wid >> 1;
    const int wn = wid & 1;

    const uint32_t a_off = (uint32_t)(wm * 32 + (lane & 15)) * (SROW * 2) + (lane >> 4) * 16;
    const uint32_t b_row = (uint32_t)(wn * 64 + (lane & 7) + ((lane >> 4) << 3));
    const uint32_t b_off = b_row * (SROW * 2) + ((lane >> 3) & 1) * 16;

    __shared__ unsigned int sh_item;

    for (;;) {
        __syncthreads();   // protect sh_item + smem reuse across items
        if (tid == 0) sh_item = atomicAdd(&g_work, 1u);
        __syncthreads();
        const unsigned int item = sh_item;
        if (item >= NITEMS) break;
        const int m0 = (int)(item >> 6) * BM;
        const int ct = (int)(item & 63);
        const int n0 = ct * BN;

        load_chunk(0, 0, m0, n0, sb, tid);
        load_chunk(1, 1, m0, n0, sb, tid);
        load_chunk(2, 2, m0, n0, sb, tid);

        float acc[2][8][4];
        #pragma unroll
        for (int nf = 0; nf < 8; nf++) {
            int col = n0 + wn * 64 + nf * 8 + (lane & 3) * 2;
            float2 h = *(const float2*)(&g_halfE2[col]);
            acc[0][nf][0] = -h.x; acc[0][nf][1] = -h.y;
            acc[0][nf][2] = -h.x; acc[0][nf][3] = -h.y;
            acc[1][nf][0] = -h.x; acc[1][nf][1] = -h.y;
            acc[1][nf][2] = -h.x; acc[1][nf][3] = -h.y;
        }

        for (int c = 0; c < KCH; ++c) {
            const int pa = KCH - 1 - c;
            if (pa >= 2)      asm volatile("cp.async.wait_group 2;" ::: "memory");
            else if (pa == 1) asm volatile("cp.async.wait_group 1;" ::: "memory");
            else              asm volatile("cp.async.wait_group 0;" ::: "memory");
            __syncthreads();

            const uint32_t stA = sb + (c & 3) * STAGE_SZ;
            const uint32_t stB = stA + STAGE_A;
            #pragma unroll
            for (int ks = 0; ks < 2; ks++) {
                uint32_t a[2][4];
                ldm_x4(stA + a_off + ks * 32, a[0][0], a[0][1], a[0][2], a[0][3]);
                ldm_x4(stA + a_off + ks * 32 + 16 * (SROW * 2),
                       a[1][0], a[1][1], a[1][2], a[1][3]);
                uint32_t b[8][2];
                #pragma unroll
                for (int np = 0; np < 4; np++) {
                    uint32_t r0, r1, r2, r3;
                    ldm_x4(stB + b_off + ks * 32 + np * (16 * SROW * 2), r0, r1, r2, r3);
                    b[np * 2][0] = r0; b[np * 2][1] = r1;
                    b[np * 2 + 1][0] = r2; b[np * 2 + 1][1] = r3;
                }
                #pragma unroll
                for (int mf = 0; mf < 2; mf++)
                    #pragma unroll
                    for (int nf = 0; nf < 8; nf++)
                        mma16816(acc[mf][nf], a[mf], b[nf]);
            }
            if (c + 3 < KCH) load_chunk(c + 3, (c + 3) & 3, m0, n0, sb, tid);
        }

        // ---- per-item top-2 epilogue ----
        float t1v[4], t2v[4];
        int   t1i[4], t2i[4];
        #pragma unroll
        for (int s = 0; s < 4; s++) { t1v[s] = -3.0e38f; t2v[s] = -3.0e38f; t1i[s] = 0; t2i[s] = 0; }
        #pragma unroll
        for (int mf = 0; mf < 2; mf++)
            #pragma unroll
            for (int h = 0; h < 2; h++) {
                int s = mf * 2 + h;
                #pragma unroll
                for (int nf = 0; nf < 8; nf++) {
                    int colb = n0 + wn * 64 + nf * 8 + (lane & 3) * 2;
                    float v0 = acc[mf][nf][h * 2 + 0];
                    float v1 = acc[mf][nf][h * 2 + 1];
                    if (v0 > t1v[s]) { t2v[s] = t1v[s]; t2i[s] = t1i[s]; t1v[s] = v0; t1i[s] = colb; }
                    else if (v0 > t2v[s]) { t2v[s] = v0; t2i[s] = colb; }
                    if (v1 > t1v[s]) { t2v[s] = t1v[s]; t2i[s] = t1i[s]; t1v[s] = v1; t1i[s] = colb + 1; }
                    else if (v1 > t2v[s]) { t2v[s] = v1; t2i[s] = colb + 1; }
                }
            }
        #pragma unroll
        for (int s = 0; s < 4; s++) {
            #pragma unroll
            for (int d = 1; d <= 2; d <<= 1) {
                float o1v = __shfl_xor_sync(0xffffffffu, t1v[s], d);
                int   o1i = __shfl_xor_sync(0xffffffffu, t1i[s], d);
                float o2v = __shfl_xor_sync(0xffffffffu, t2v[s], d);
                int   o2i = __shfl_xor_sync(0xffffffffu, t2i[s], d);
                merge2(t1v[s], t1i[s], t2v[s], t2i[s], o1v, o1i, o2v, o2i);
            }
        }
        __syncthreads();
        float* c_v = (float*)smem;            // [128][2][2]
        int*   c_i = (int*)(smem + 2048);     // [128][2][2]
        if ((lane & 3) == 0) {
            #pragma unroll
            for (int s = 0; s < 4; s++) {
                int mf = s >> 1, h = s & 1;
                int row = wm * 32 + mf * 16 + h * 8 + (lane >> 2);
                c_v[(row * 2 + wn) * 2 + 0] = t1v[s];
                c_v[(row * 2 + wn) * 2 + 1] = t2v[s];
                c_i[(row * 2 + wn) * 2 + 0] = t1i[s];
                c_i[(row * 2 + wn) * 2 + 1] = t2i[s];
            }
        }
        __syncthreads();
        if (tid < BM) {
            float v1 = c_v[(tid * 2) * 2 + 0], v2 = c_v[(tid * 2) * 2 + 1];
            int   i1 = c_i[(tid * 2) * 2 + 0], i2 = c_i[(tid * 2) * 2 + 1];
            merge2(v1, i1, v2, i2,
                   c_v[(tid * 2 + 1) * 2 + 0], c_i[(tid * 2 + 1) * 2 + 0],
                   c_v[(tid * 2 + 1) * 2 + 1], c_i[(tid * 2 + 1) * 2 + 1]);
            g_cand[(size_t)ct * NTOK + m0 + tid] =
                make_float4(v1, v2, __int_as_float(i1), __int_as_float(i2));
        }
    }
}

// ---------------------------------------------------------------------------
// K1b: merge 64 per-ct candidates + exact fp32 refine (one warp per token)
// ---------------------------------------------------------------------------
__global__ void k_refine(const float* __restrict__ X, const float* __restrict__ E) {
    const int n = blockIdx.x * 8 + (threadIdx.x >> 5);
    const int lane = threadIdx.x & 31;

    float4 cA = g_cand[(size_t)lane * NTOK + n];
    float4 cB = g_cand[(size_t)(lane + 32) * NTOK + n];
    float v1 = cA.x, v2 = cA.y;
    int   i1 = __float_as_int(cA.z), i2 = __float_as_int(cA.w);
    merge2(v1, i1, v2, i2, cB.x, __float_as_int(cB.z), cB.y, __float_as_int(cB.w));
    #pragma unroll
    for (int d = 16; d; d >>= 1) {
        float o1v = __shfl_xor_sync(0xffffffffu, v1, d);
        int   o1i = __shfl_xor_sync(0xffffffffu, i1, d);
        float o2v = __shfl_xor_sync(0xffffffffu, v2, d);
        int   o2i = __shfl_xor_sync(0xffffffffu, i2, d);
        merge2(v1, i1, v2, i2, o1v, o1i, o2v, o2i);
    }
    const int bi = __shfl_sync(0xffffffffu, i1, 0);
    const int si = __shfl_sync(0xffffffffu, i2, 0);

    const float* x  = X + (size_t)n * DDIM;
    const float* e1 = E + (size_t)bi * DDIM;
    const float* e2 = E + (size_t)si * DDIM;
    float s1 = 0.f, s2 = 0.f;
    #pragma unroll
    for (int i = 0; i < DDIM / 32; i++) {
        float xv = x[lane + i * 32];
        s1 = fmaf(xv, e1[lane + i * 32], s1);
        s2 = fmaf(xv, e2[lane + i * 32], s2);
    }
    #pragma unroll
    for (int o = 16; o; o >>= 1) {
        s1 += __shfl_xor_sync(0xffffffffu, s1, o);
        s2 += __shfl_xor_sync(0xffffffffu, s2, o);
    }
    if (lane == 0) {
        float sc1 = s1 - g_halfE2[bi];
        float sc2 = s2 - g_halfE2[si];
        int idx = bi;
        if (sc2 > sc1 || (sc2 == sc1 && si < bi)) idx = si;
        g_idx[n] = idx;
    }
}

// ---------------------------------------------------------------------------
// K2: gather + straight-through output, loss, scatter cs/dw
// ---------------------------------------------------------------------------
__global__ void k_scatter(const float* __restrict__ X, const float* __restrict__ E,
                          float* __restrict__ out) {
    int n = blockIdx.x;
    int k = g_idx[n];
    int t = threadIdx.x;

    float4 x = *(const float4*)(X + (size_t)n * DDIM + t * 4);
    float4 q = *(const float4*)(E + (size_t)k * DDIM + t * 4);
    float dx = q.x - x.x, dy = q.y - x.y, dz = q.z - x.z, dw = q.w - x.w;
    float4 o;
    o.x = x.x + dx; o.y = x.y + dy; o.z = x.z + dz; o.w = x.w + dw;
    *(float4*)(out + OQ + (size_t)n * DDIM + t * 4) = o;

    float ls = dx * dx + dy * dy + dz * dz + dw * dw;
    __shared__ float sh[4];
    int lane = t & 31, w = t >> 5;
    #pragma unroll
    for (int oo = 16; oo; oo >>= 1) ls += __shfl_down_sync(0xffffffffu, ls, oo);
    if (lane == 0) sh[w] = ls;
    __syncthreads();
    if (t == 0) {
        float s = sh[0] + sh[1] + sh[2] + sh[3];
        atomicAdd(&g_loss, (double)s);
        atomicAdd(&g_cs[k], 1.0f);
    }

    float* dwr = g_dw + (size_t)k * DDIM + t * 4;
    atomicAdd(dwr + 0, x.x);
    atomicAdd(dwr + 1, x.y);
    atomicAdd(dwr + 2, x.z);
    atomicAdd(dwr + 3, x.w);
}

// K3: stats
__global__ __launch_bounds__(1024, 1)
void k_stats(const float* __restrict__ ema_cs, float* __restrict__ out) {
    int t = threadIdx.x;
    float pre[8];
    double s_pre = 0.0, s_ent = 0.0;
    #pragma unroll
    for (int i = 0; i < 8; i++) {
        int k = t + i * 1024;
        float cs = g_cs[k];
        pre[i] = ema_cs[k] * DECAY + ONE_MINUS_DECAY * cs;
        s_pre += (double)pre[i];
        float p = cs * (1.0f / (float)NTOK);
        s_ent += (double)(p * logf(p + 1e-10f));
    }
    __shared__ double shp[32], she[32];
    int lane = t & 31, w = t >> 5;
    #pragma unroll
    for (int o = 16; o; o >>= 1) {
        s_pre += __shfl_down_sync(0xffffffffu, s_pre, o);
        s_ent += __shfl_down_sync(0xffffffffu, s_ent, o);
    }
    if (lane == 0) { shp[w] = s_pre; she[w] = s_ent; }
    __syncthreads();
    __shared__ double tot_pre_s, tot_ent_s;
    if (w == 0) {
        double vp = shp[lane], ve = she[lane];
        #pragma unroll
        for (int o = 16; o; o >>= 1) {
            vp += __shfl_down_sync(0xffffffffu, vp, o);
            ve += __shfl_down_sync(0xffffffffu, ve, o);
        }
        if (lane == 0) { tot_pre_s = vp; tot_ent_s = ve; }
    }
    __syncthreads();
    float ntot = (float)tot_pre_s;
    float denom = ntot + (float)KCODE * EPS;
    #pragma unroll
    for (int i = 0; i < 8; i++) {
        int k = t + i * 1024;
        float ncs = (pre[i] + EPS) / denom * ntot;
        g_newcs[k] = ncs;
        out[OC + k] = ncs;
    }
    if (t == 0) {
        out[OL] = (float)(COMMIT * g_loss / ((double)NTOK * (double)DDIM));
        out[OP] = (float)exp(-tot_ent_s);
    }
}

// K4: EMA updates (float2: OE/OW only 8B aligned)
__global__ void k_ema(const float* __restrict__ ema_w, float* __restrict__ out) {
    size_t gi = (size_t)blockIdx.x * blockDim.x + threadIdx.x;
    int k = (int)(gi >> 8);
    float ncs = g_newcs[k];
    float2 w = *(const float2*)(ema_w + gi * 2);
    float2 d = *(const float2*)(g_dw + gi * 2);
    float2 ew;
    ew.x = w.x * DECAY + ONE_MINUS_DECAY * d.x;
    ew.y = w.y * DECAY + ONE_MINUS_DECAY * d.y;
    *(float2*)(out + OW + gi * 2) = ew;
    float2 eb;
    eb.x = ew.x / ncs; eb.y = ew.y / ncs;
    *(float2*)(out + OE + gi * 2) = eb;
}

// ---------------------------------------------------------------------------
extern "C" void kernel_launch(void* const* d_in, const int* in_sizes, int n_in,
                              void* d_out, int out_size) {
    const float* X   = (const float*)d_in[0];
    const float* E   = (const float*)d_in[1];
    const float* ECS = (const float*)d_in[2];
    const float* EW  = (const float*)d_in[3];
    float* out = (float*)d_out;

    cudaFuncSetAttribute(k_gemm, cudaFuncAttributeMaxDynamicSharedMemorySize, GEMM_SMEM);

    k_prep<<<KCODE, 256>>>(E);
    k_cvtx<<<(NTOK * DDIM) / 256, 256>>>(X);
    k_gemm<<<296, 256, GEMM_SMEM>>>();
    k_refine<<<NTOK / 8, 256>>>(X, E);
    k_scatter<<<NTOK, 128>>>(X, E, out);
    k_stats<<<1, 1024>>>(ECS, out);
    k_ema<<<(KCODE * DDIM / 2) / 256, 256>>>(EW, out);
}

// round 8
// speedup vs baseline: 2.8111x; 2.1543x over previous
#include <cuda_runtime.h>
#include <cuda_bf16.h>
#include <math.h>
#include <stdint.h>

// ---------------------------------------------------------------------------
// VectorQuantizerEMA (N=32768, K=8192, D=512)
// Single bf16 GEMM (exact -|e|^2/2 in acc init) + global top-4 exact refine.
// ---------------------------------------------------------------------------
#define NTOK 32768
#define KCODE 8192
#define DDIM 512

#define DECAY 0.99f
#define ONE_MINUS_DECAY 0.01f
#define EPS 1e-5f
#define COMMIT 0.25f

#define OQ  ((size_t)0)
#define OL  ((size_t)(NTOK) * DDIM)
#define OP  (OL + 1)
#define OE  (OP + 1)
#define OC  (OE + (size_t)KCODE * DDIM)
#define OW  (OC + KCODE)

// ------------------------- device scratch (no alloc) -----------------------
__device__ float          g_halfE2[KCODE];
__device__ int            g_idx[NTOK];
__device__ float          g_cs[KCODE];
__device__ float          g_newcs[KCODE];
__device__ float          g_dw[(size_t)KCODE * DDIM];
__device__ double         g_loss;
__device__ __nv_bfloat16  g_xb[(size_t)NTOK * DDIM];
__device__ __nv_bfloat16  g_eb[(size_t)KCODE * DDIM];
__device__ float4         g_cand[(size_t)NTOK * 64];   // [token][ct] {v1,v2,i1,i2}

// ------------------------- helpers -----------------------------------------
__device__ __forceinline__ uint32_t smem_u32(const void* p) {
    uint32_t a;
    asm("{ .reg .u64 t; cvta.to.shared.u64 t, %1; cvt.u32.u64 %0, t; }" : "=r"(a) : "l"(p));
    return a;
}
__device__ __forceinline__ void cp16(uint32_t dst, const void* src) {
    asm volatile("cp.async.cg.shared.global [%0], [%1], 16;" :: "r"(dst), "l"(src));
}
#define CP_COMMIT() asm volatile("cp.async.commit_group;" ::: "memory")

__device__ __forceinline__ void ldm_x4(uint32_t addr, uint32_t& r0, uint32_t& r1,
                                       uint32_t& r2, uint32_t& r3) {
    asm volatile("ldmatrix.sync.aligned.m8n8.x4.shared.b16 {%0,%1,%2,%3}, [%4];"
                 : "=r"(r0), "=r"(r1), "=r"(r2), "=r"(r3) : "r"(addr));
}
__device__ __forceinline__ void mma16816(float* d, const uint32_t* a, const uint32_t* b) {
    asm volatile("mma.sync.aligned.m16n8k16.row.col.f32.bf16.bf16.f32 "
                 "{%0,%1,%2,%3}, {%4,%5,%6,%7}, {%8,%9}, {%0,%1,%2,%3};"
                 : "+f"(d[0]), "+f"(d[1]), "+f"(d[2]), "+f"(d[3])
                 : "r"(a[0]), "r"(a[1]), "r"(a[2]), "r"(a[3]), "r"(b[0]), "r"(b[1]));
}
__device__ __forceinline__ void merge2(float& t1v, int& t1i, float& t2v, int& t2i,
                                       float o1v, int o1i, float o2v, int o2i) {
    if (o1v > t1v) {
        float n2v = t1v; int n2i = t1i;
        if (o2v > n2v) { n2v = o2v; n2i = o2i; }
        t1v = o1v; t1i = o1i; t2v = n2v; t2i = n2i;
    } else if (o1v > t2v) {
        t2v = o1v; t2i = o1i;
    }
}
// insert (ov,oi) into descending sorted-4
__device__ __forceinline__ void ins4(float* v, int* ix, float ov, int oi) {
    if (ov > v[3]) {
        if (ov > v[2]) {
            v[3] = v[2]; ix[3] = ix[2];
            if (ov > v[1]) {
                v[2] = v[1]; ix[2] = ix[1];
                if (ov > v[0]) { v[1] = v[0]; ix[1] = ix[0]; v[0] = ov; ix[0] = oi; }
                else { v[1] = ov; ix[1] = oi; }
            } else { v[2] = ov; ix[2] = oi; }
        } else { v[3] = ov; ix[3] = oi; }
    }
}

// ---------------------------------------------------------------------------
// K0a: E -> bf16, half-norms, zero scratch
// ---------------------------------------------------------------------------
__global__ void k_prep(const float* __restrict__ E) {
    int k = blockIdx.x;
    int t = threadIdx.x;
    const float* row = E + (size_t)k * DDIM;
    float e0 = row[t], e1 = row[t + 256];

    g_eb[(size_t)k * DDIM + t]       = __float2bfloat16_rn(e0);
    g_eb[(size_t)k * DDIM + t + 256] = __float2bfloat16_rn(e1);

    float s = e0 * e0 + e1 * e1;
    __shared__ float sh[8];
    int lane = t & 31, w = t >> 5;
    #pragma unroll
    for (int o = 16; o; o >>= 1) s += __shfl_down_sync(0xffffffffu, s, o);
    if (lane == 0) sh[w] = s;
    __syncthreads();
    if (w == 0) {
        float v = (lane < 8) ? sh[lane] : 0.f;
        #pragma unroll
        for (int o = 4; o; o >>= 1) v += __shfl_down_sync(0xffffffffu, v, o);
        if (lane == 0) g_halfE2[k] = 0.5f * v;
    }
    float* dwr = g_dw + (size_t)k * DDIM;
    dwr[t] = 0.f;
    dwr[t + 256] = 0.f;
    if (t == 0) g_cs[k] = 0.f;
    if (k == 0 && t == 0) g_loss = 0.0;
}

// K0b: X -> bf16
__global__ void k_cvtx(const float* __restrict__ X) {
    size_t i = (size_t)blockIdx.x * 256 + threadIdx.x;
    g_xb[i] = __float2bfloat16_rn(X[i]);
}

// ---------------------------------------------------------------------------
// K1: persistent bf16 GEMM + per-tile top-2.
// Item = (m-tile 0..255, ct 0..63): 128x128 tile, 16 BK=32 chunks.
// 296 CTAs, static contiguous item ranges, flat chunk stream across items
// (no inter-item pipeline bubble). 4-stage cp.async ring, 8 warps (4x2).
// ---------------------------------------------------------------------------
#define BM 128
#define BN 128
#define BK 32
#define KCH 16
#define NITEMS (256 * 64)
#define NCTA 296
#define SROW 40                      // bf16 stride (32 + 8 pad) = 80 B
#define STAGE_A (BM * SROW * 2)      // 10240 B
#define STAGE_SZ (2 * STAGE_A)       // 20480 B
#define NSTAGE 4
#define RED_OFF (NSTAGE * STAGE_SZ)         // dedicated reduce buffer
#define GEMM_SMEM (RED_OFF + 4096)          // 86016 B

__device__ __forceinline__ void load_flat(int gflat, int i0, uint32_t sb, int tid) {
    const int item = i0 + (gflat >> 4);
    const int kc = gflat & 15;
    const int m0 = (item >> 6) * BM;
    const int n0 = (item & 63) * BN;
    const int koff = kc * BK;
    const uint32_t stA = sb + (gflat & 3) * STAGE_SZ;
    const uint32_t stB = stA + STAGE_A;
    #pragma unroll
    for (int i = 0; i < 2; i++) {
        int idx = tid + i * 256;
        int row = idx >> 2, c = idx & 3;
        cp16(stA + row * (SROW * 2) + c * 16,
             g_xb + (size_t)(m0 + row) * DDIM + koff + c * 8);
        cp16(stB + row * (SROW * 2) + c * 16,
             g_eb + (size_t)(n0 + row) * DDIM + koff + c * 8);
    }
    CP_COMMIT();
}

__global__ __launch_bounds__(256, 2)
void k_gemm() {
    extern __shared__ char smem[];
    const uint32_t sb = smem_u32(smem);
    const int tid = threadIdx.x;
    const int wid = tid >> 5;
    const int lane = tid & 31;
    const int wm = wid >> 1;
    const int wn = wid & 1;
    const int bid = blockIdx.x;

    // static contiguous item range: 16384 = 296*55 + 104
    const int base = NITEMS / NCTA;              // 55
    const int rem  = NITEMS - base * NCTA;       // 104
    const int i0   = bid * base + (bid < rem ? bid : rem);
    const int cnt  = base + (bid < rem ? 1 : 0);
    const int T    = cnt * KCH;

    const uint32_t a_off = (uint32_t)(wm * 32 + (lane & 15)) * (SROW * 2) + (lane >> 4) * 16;
    const uint32_t b_row = (uint32_t)(wn * 64 + (lane & 7) + ((lane >> 4) << 3));
    const uint32_t b_off = b_row * (SROW * 2) + ((lane >> 3) & 1) * 16;

    load_flat(0, i0, sb, tid);
    load_flat(1, i0, sb, tid);
    load_flat(2, i0, sb, tid);

    float acc[2][8][4];

    for (int g = 0; g < T; ++g) {
        const int kc = g & 15;
        const int item = i0 + (g >> 4);
        const int n0 = (item & 63) * BN;

        if (kc == 0) {
            #pragma unroll
            for (int nf = 0; nf < 8; nf++) {
                int col = n0 + wn * 64 + nf * 8 + (lane & 3) * 2;
                float2 h = *(const float2*)(&g_halfE2[col]);
                acc[0][nf][0] = -h.x; acc[0][nf][1] = -h.y;
                acc[0][nf][2] = -h.x; acc[0][nf][3] = -h.y;
                acc[1][nf][0] = -h.x; acc[1][nf][1] = -h.y;
                acc[1][nf][2] = -h.x; acc[1][nf][3] = -h.y;
            }
        }

        const int pa = T - 1 - g;
        if (pa >= 2)      asm volatile("cp.async.wait_group 2;" ::: "memory");
        else if (pa == 1) asm volatile("cp.async.wait_group 1;" ::: "memory");
        else              asm volatile("cp.async.wait_group 0;" ::: "memory");
        __syncthreads();

        const uint32_t stA = sb + (g & 3) * STAGE_SZ;
        const uint32_t stB = stA + STAGE_A;
        #pragma unroll
        for (int ks = 0; ks < 2; ks++) {
            uint32_t a[2][4];
            ldm_x4(stA + a_off + ks * 32, a[0][0], a[0][1], a[0][2], a[0][3]);
            ldm_x4(stA + a_off + ks * 32 + 16 * (SROW * 2),
                   a[1][0], a[1][1], a[1][2], a[1][3]);
            uint32_t b[8][2];
            #pragma unroll
            for (int np = 0; np < 4; np++) {
                uint32_t r0, r1, r2, r3;
                ldm_x4(stB + b_off + ks * 32 + np * (16 * SROW * 2), r0, r1, r2, r3);
                b[np * 2][0] = r0; b[np * 2][1] = r1;
                b[np * 2 + 1][0] = r2; b[np * 2 + 1][1] = r3;
            }
            #pragma unroll
            for (int mf = 0; mf < 2; mf++)
                #pragma unroll
                for (int nf = 0; nf < 8; nf++)
                    mma16816(acc[mf][nf], a[mf], b[nf]);
        }
        if (g + 3 < T) load_flat(g + 3, i0, sb, tid);

        if (kc == KCH - 1) {
            // ---- per-item top-2 epilogue (reduce buffer is OUTSIDE stages) ----
            const int m0 = (item >> 6) * BM;
            const int ct = item & 63;
            float t1v[4], t2v[4];
            int   t1i[4], t2i[4];
            #pragma unroll
            for (int s = 0; s < 4; s++) { t1v[s] = -3.0e38f; t2v[s] = -3.0e38f; t1i[s] = 0; t2i[s] = 0; }
            #pragma unroll
            for (int mf = 0; mf < 2; mf++)
                #pragma unroll
                for (int h = 0; h < 2; h++) {
                    int s = mf * 2 + h;
                    #pragma unroll
                    for (int nf = 0; nf < 8; nf++) {
                        int colb = n0 + wn * 64 + nf * 8 + (lane & 3) * 2;
                        float v0 = acc[mf][nf][h * 2 + 0];
                        float v1 = acc[mf][nf][h * 2 + 1];
                        if (v0 > t1v[s]) { t2v[s] = t1v[s]; t2i[s] = t1i[s]; t1v[s] = v0; t1i[s] = colb; }
                        else if (v0 > t2v[s]) { t2v[s] = v0; t2i[s] = colb; }
                        if (v1 > t1v[s]) { t2v[s] = t1v[s]; t2i[s] = t1i[s]; t1v[s] = v1; t1i[s] = colb + 1; }
                        else if (v1 > t2v[s]) { t2v[s] = v1; t2i[s] = colb + 1; }
                    }
                }
            #pragma unroll
            for (int s = 0; s < 4; s++) {
                #pragma unroll
                for (int d = 1; d <= 2; d <<= 1) {
                    float o1v = __shfl_xor_sync(0xffffffffu, t1v[s], d);
                    int   o1i = __shfl_xor_sync(0xffffffffu, t1i[s], d);
                    float o2v = __shfl_xor_sync(0xffffffffu, t2v[s], d);
                    int   o2i = __shfl_xor_sync(0xffffffffu, t2i[s], d);
                    merge2(t1v[s], t1i[s], t2v[s], t2i[s], o1v, o1i, o2v, o2i);
                }
            }
            __syncthreads();
            float* c_v = (float*)(smem + RED_OFF);            // [128][2][2]
            int*   c_i = (int*)(smem + RED_OFF + 2048);       // [128][2][2]
            if ((lane & 3) == 0) {
                #pragma unroll
                for (int s = 0; s < 4; s++) {
                    int mf = s >> 1, h = s & 1;
                    int row = wm * 32 + mf * 16 + h * 8 + (lane >> 2);
                    c_v[(row * 2 + wn) * 2 + 0] = t1v[s];
                    c_v[(row * 2 + wn) * 2 + 1] = t2v[s];
                    c_i[(row * 2 + wn) * 2 + 0] = t1i[s];
                    c_i[(row * 2 + wn) * 2 + 1] = t2i[s];
                }
            }
            __syncthreads();
            if (tid < BM) {
                float v1 = c_v[(tid * 2) * 2 + 0], v2 = c_v[(tid * 2) * 2 + 1];
                int   i1 = c_i[(tid * 2) * 2 + 0], i2 = c_i[(tid * 2) * 2 + 1];
                merge2(v1, i1, v2, i2,
                       c_v[(tid * 2 + 1) * 2 + 0], c_i[(tid * 2 + 1) * 2 + 0],
                       c_v[(tid * 2 + 1) * 2 + 1], c_i[(tid * 2 + 1) * 2 + 1]);
                g_cand[(size_t)(m0 + tid) * 64 + ct] =
                    make_float4(v1, v2, __int_as_float(i1), __int_as_float(i2));
            }
        }
    }
}

// ---------------------------------------------------------------------------
// K1b: merge 64 tile-candidates -> global top-4, exact fp32 rescore.
// One warp per token.
// ---------------------------------------------------------------------------
__global__ void k_refine(const float* __restrict__ X, const float* __restrict__ E) {
    const int n = blockIdx.x * 8 + (threadIdx.x >> 5);
    const int lane = threadIdx.x & 31;

    float4 cA = g_cand[(size_t)n * 64 + lane];
    float4 cB = g_cand[(size_t)n * 64 + lane + 32];

    float v[4]; int ix[4];
    v[0] = -3.0e38f; v[1] = -3.0e38f; v[2] = -3.0e38f; v[3] = -3.0e38f;
    ix[0] = ix[1] = ix[2] = ix[3] = 0;
    ins4(v, ix, cA.x, __float_as_int(cA.z));
    ins4(v, ix, cA.y, __float_as_int(cA.w));
    ins4(v, ix, cB.x, __float_as_int(cB.z));
    ins4(v, ix, cB.y, __float_as_int(cB.w));

    #pragma unroll
    for (int d = 16; d; d >>= 1) {
        float ov[4]; int oi[4];
        #pragma unroll
        for (int s = 0; s < 4; s++) {
            ov[s] = __shfl_xor_sync(0xffffffffu, v[s], d);
            oi[s] = __shfl_xor_sync(0xffffffffu, ix[s], d);
        }
        #pragma unroll
        for (int s = 0; s < 4; s++) ins4(v, ix, ov[s], oi[s]);
    }

    // exact fp32 rescore of the 4 candidates (all lanes hold identical lists)
    float xr[16];
    const float* x = X + (size_t)n * DDIM;
    #pragma unroll
    for (int i = 0; i < 16; i++) xr[i] = x[lane + i * 32];

    float sc[4];
    #pragma unroll
    for (int c = 0; c < 4; c++) {
        const float* e = E + (size_t)ix[c] * DDIM;
        float s = 0.f;
        #pragma unroll
        for (int i = 0; i < 16; i++) s = fmaf(xr[i], e[lane + i * 32], s);
        #pragma unroll
        for (int o = 16; o; o >>= 1) s += __shfl_xor_sync(0xffffffffu, s, o);
        sc[c] = s - g_halfE2[ix[c]];
    }
    if (lane == 0) {
        float bv = sc[0]; int bi = ix[0];
        #pragma unroll
        for (int c = 1; c < 4; c++) {
            if (sc[c] > bv || (sc[c] == bv && ix[c] < bi)) { bv = sc[c]; bi = ix[c]; }
        }
        g_idx[n] = bi;
    }
}

// ---------------------------------------------------------------------------
// K2: gather + straight-through output, loss, scatter cs/dw
// ---------------------------------------------------------------------------
__global__ void k_scatter(const float* __restrict__ X, const float* __restrict__ E,
                          float* __restrict__ out) {
    int n = blockIdx.x;
    int k = g_idx[n];
    int t = threadIdx.x;

    float4 x = *(const float4*)(X + (size_t)n * DDIM + t * 4);
    float4 q = *(const float4*)(E + (size_t)k * DDIM + t * 4);
    float dx = q.x - x.x, dy = q.y - x.y, dz = q.z - x.z, dw = q.w - x.w;
    float4 o;
    o.x = x.x + dx; o.y = x.y + dy; o.z = x.z + dz; o.w = x.w + dw;
    *(float4*)(out + OQ + (size_t)n * DDIM + t * 4) = o;

    float ls = dx * dx + dy * dy + dz * dz + dw * dw;
    __shared__ float sh[4];
    int lane = t & 31, w = t >> 5;
    #pragma unroll
    for (int oo = 16; oo; oo >>= 1) ls += __shfl_down_sync(0xffffffffu, ls, oo);
    if (lane == 0) sh[w] = ls;
    __syncthreads();
    if (t == 0) {
        float s = sh[0] + sh[1] + sh[2] + sh[3];
        atomicAdd(&g_loss, (double)s);
        atomicAdd(&g_cs[k], 1.0f);
    }

    float* dwr = g_dw + (size_t)k * DDIM + t * 4;
    atomicAdd(dwr + 0, x.x);
    atomicAdd(dwr + 1, x.y);
    atomicAdd(dwr + 2, x.z);
    atomicAdd(dwr + 3, x.w);
}

// K3: stats
__global__ __launch_bounds__(1024, 1)
void k_stats(const float* __restrict__ ema_cs, float* __restrict__ out) {
    int t = threadIdx.x;
    float pre[8];
    double s_pre = 0.0, s_ent = 0.0;
    #pragma unroll
    for (int i = 0; i < 8; i++) {
        int k = t + i * 1024;
        float cs = g_cs[k];
        pre[i] = ema_cs[k] * DECAY + ONE_MINUS_DECAY * cs;
        s_pre += (double)pre[i];
        float p = cs * (1.0f / (float)NTOK);
        s_ent += (double)(p * logf(p + 1e-10f));
    }
    __shared__ double shp[32], she[32];
    int lane = t & 31, w = t >> 5;
    #pragma unroll
    for (int o = 16; o; o >>= 1) {
        s_pre += __shfl_down_sync(0xffffffffu, s_pre, o);
        s_ent += __shfl_down_sync(0xffffffffu, s_ent, o);
    }
    if (lane == 0) { shp[w] = s_pre; she[w] = s_ent; }
    __syncthreads();
    __shared__ double tot_pre_s, tot_ent_s;
    if (w == 0) {
        double vp = shp[lane], ve = she[lane];
        #pragma unroll
        for (int o = 16; o; o >>= 1) {
            vp += __shfl_down_sync(0xffffffffu, vp, o);
            ve += __shfl_down_sync(0xffffffffu, ve, o);
        }
        if (lane == 0) { tot_pre_s = vp; tot_ent_s = ve; }
    }
    __syncthreads();
    float ntot = (float)tot_pre_s;
    float denom = ntot + (float)KCODE * EPS;
    #pragma unroll
    for (int i = 0; i < 8; i++) {
        int k = t + i * 1024;
        float ncs = (pre[i] + EPS) / denom * ntot;
        g_newcs[k] = ncs;
        out[OC + k] = ncs;
    }
    if (t == 0) {
        out[OL] = (float)(COMMIT * g_loss / ((double)NTOK * (double)DDIM));
        out[OP] = (float)exp(-tot_ent_s);
    }
}

// K4: EMA updates (float2: OE/OW only 8B aligned)
__global__ void k_ema(const float* __restrict__ ema_w, float* __restrict__ out) {
    size_t gi = (size_t)blockIdx.x * blockDim.x + threadIdx.x;
    int k = (int)(gi >> 8);
    float ncs = g_newcs[k];
    float2 w = *(const float2*)(ema_w + gi * 2);
    float2 d = *(const float2*)(g_dw + gi * 2);
    float2 ew;
    ew.x = w.x * DECAY + ONE_MINUS_DECAY * d.x;
    ew.y = w.y * DECAY + ONE_MINUS_DECAY * d.y;
    *(float2*)(out + OW + gi * 2) = ew;
    float2 eb;
    eb.x = ew.x / ncs; eb.y = ew.y / ncs;
    *(float2*)(out + OE + gi * 2) = eb;
}

// ---------------------------------------------------------------------------
extern "C" void kernel_launch(void* const* d_in, const int* in_sizes, int n_in,
                              void* d_out, int out_size) {
    const float* X   = (const float*)d_in[0];
    const float* E   = (const float*)d_in[1];
    const float* ECS = (const float*)d_in[2];
    const float* EW  = (const float*)d_in[3];
    float* out = (float*)d_out;

    cudaFuncSetAttribute(k_gemm, cudaFuncAttributeMaxDynamicSharedMemorySize, GEMM_SMEM);

    k_prep<<<KCODE, 256>>>(E);
    k_cvtx<<<(NTOK * DDIM) / 256, 256>>>(X);
    k_gemm<<<NCTA, 256, GEMM_SMEM>>>();
    k_refine<<<NTOK / 8, 256>>>(X, E);
    k_scatter<<<NTOK, 128>>>(X, E, out);
    k_stats<<<1, 1024>>>(ECS, out);
    k_ema<<<(KCODE * DDIM / 2) / 256, 256>>>(EW, out);
}